// round 2
// baseline (speedup 1.0000x reference)
#include <cuda_runtime.h>
#include <cstdint>

#define BB 64          // batch
#define CC 4096        // capsules
#define IND 512        // in_dim (K)
#define OO 16          // caps_len (N)
#define TI 32          // i-tile staged in smem
#define NTILES (IND / TI)   // 16
#define NTH 64         // threads per CTA (one capsule per CTA)

// ---- packed f32x2 helpers (sm_100+ PTX) ----
__device__ __forceinline__ uint64_t pack_dup(float x) {
    uint64_t r;
    asm("mov.b64 %0, {%1, %1};" : "=l"(r) : "f"(x));
    return r;
}
__device__ __forceinline__ void fma2(uint64_t& d, uint64_t a, uint64_t b) {
    asm("fma.rn.f32x2 %0, %1, %2, %0;" : "+l"(d) : "l"(a), "l"(b));
}
__device__ __forceinline__ void unpack2(uint64_t v, float& lo, float& hi) {
    asm("mov.b64 {%0, %1}, %2;" : "=f"(lo), "=f"(hi) : "l"(v));
}

// ---- 16B cp.async (LDGSTS) ----
__device__ __forceinline__ void cp16(void* dst_smem, const void* src) {
    uint32_t d = (uint32_t)__cvta_generic_to_shared(dst_smem);
    asm volatile("cp.async.ca.shared.global [%0], [%1], 16;"
                 :: "r"(d), "l"(src) : "memory");
}
__device__ __forceinline__ void cp_commit() {
    asm volatile("cp.async.commit_group;" ::: "memory");
}
__device__ __forceinline__ void cp_wait0() {
    asm volatile("cp.async.wait_group 0;" ::: "memory");
}

__global__ __launch_bounds__(NTH, 8)
void primarycaps_kernel(const float* __restrict__ x,
                        const float* __restrict__ W,
                        const float* __restrict__ bias,
                        float* __restrict__ out)
{
    // x tile, double-buffered: [buf][b][slot] where slot = ii4 ^ (b&7)
    // (float4 granularity swizzle: conflict-free for both LDGSTS writes
    //  and compute-side LDS.128 reads)
    __shared__ float4 sX[2][BB * 8];   // 2 x 8KB

    const int c  = blockIdx.x;
    const int t  = threadIdx.x;
    const int bg = t & 31;             // lane -> batch row
    const int og = t >> 5;             // warp -> o half
    const int swz = bg & 7;

    // staging mapping: thread -> (b row group, float4 chunk within 32-float tile)
    const int sb   = t >> 3;           // 0..7
    const int sii4 = t & 7;            // 0..7
    const int slot = sii4 ^ sb;        // sb < 8, so (b & 7) == sb for b = sb+8k
    const float* xg0 = x + ((size_t)sb * CC + c) * IND + sii4 * 4;

    // issue tile 0
    #pragma unroll
    for (int k = 0; k < 8; ++k)
        cp16(&sX[0][(sb + 8 * k) * 8 + slot],
             xg0 + (size_t)k * 8 * CC * IND);
    cp_commit();

    // accumulators: 2 b-rows x 4 o-pairs (packed f32x2)
    uint64_t acc[2][4];
    #pragma unroll
    for (int i = 0; i < 2; ++i)
        #pragma unroll
        for (int j = 0; j < 4; ++j)
            acc[i][j] = 0ULL;

    // W[c] rows as 16B chunks: row i = 4 x ulonglong2; this warp's o-half = 2 of them
    const ulonglong2* __restrict__ Wg =
        (const ulonglong2*)(W + (size_t)c * IND * OO);
    const int wofs = og * 2;

    for (int j = 0; j < NTILES; ++j) {
        cp_wait0();            // this thread's tile-j copies landed
        __syncthreads();       // everyone's landed; everyone done computing j-1

        // issue tile j+1 into the buffer freed by tile j-1 (safe: barrier above)
        if (j + 1 < NTILES) {
            const float* xg = xg0 + (size_t)(j + 1) * TI;
            float4* dst = sX[(j + 1) & 1];
            #pragma unroll
            for (int k = 0; k < 8; ++k)
                cp16(&dst[(sb + 8 * k) * 8 + slot],
                     xg + (size_t)k * 8 * CC * IND);
            cp_commit();
        }

        // compute tile j
        const float4* __restrict__ sb4 = sX[j & 1];
        const int i0 = j * TI;
        #pragma unroll
        for (int q = 0; q < 8; ++q) {
            // x for 4 i-steps, both b-rows (conflict-free LDS.128)
            const float4 xq0 = sb4[bg * 8 + (q ^ swz)];
            const float4 xq1 = sb4[(bg + 32) * 8 + (q ^ swz)];
            const float xv0[4] = {xq0.x, xq0.y, xq0.z, xq0.w};
            const float xv1[4] = {xq1.x, xq1.y, xq1.z, xq1.w};

            #pragma unroll
            for (int r = 0; r < 4; ++r) {
                const int i = i0 + q * 4 + r;
                // broadcast LDG.128 (uniform address -> 1 line, 1 wavefront)
                const ulonglong2 wA = Wg[i * 4 + wofs];
                const ulonglong2 wB = Wg[i * 4 + wofs + 1];

                const uint64_t xd0 = pack_dup(xv0[r]);
                const uint64_t xd1 = pack_dup(xv1[r]);

                fma2(acc[0][0], xd0, wA.x);
                fma2(acc[0][1], xd0, wA.y);
                fma2(acc[0][2], xd0, wB.x);
                fma2(acc[0][3], xd0, wB.y);
                fma2(acc[1][0], xd1, wA.x);
                fma2(acc[1][1], xd1, wA.y);
                fma2(acc[1][2], xd1, wB.x);
                fma2(acc[1][3], xd1, wB.y);
            }
        }
    }

    // ---- epilogue: unpack, add bias, vector store ----
    const int o0 = og * 8;
    const float4* bias4 = (const float4*)(bias + (size_t)c * OO + o0);
    const float4 bz0 = bias4[0];
    const float4 bz1 = bias4[1];

    #pragma unroll
    for (int r = 0; r < 2; ++r) {
        float v0, v1, v2, v3, v4, v5, v6, v7;
        unpack2(acc[r][0], v0, v1);
        unpack2(acc[r][1], v2, v3);
        unpack2(acc[r][2], v4, v5);
        unpack2(acc[r][3], v6, v7);

        float4 lo = make_float4(v0 + bz0.x, v1 + bz0.y, v2 + bz0.z, v3 + bz0.w);
        float4 hi = make_float4(v4 + bz1.x, v5 + bz1.y, v6 + bz1.z, v7 + bz1.w);

        const int b = bg + r * 32;
        float* op = out + ((size_t)b * CC + c) * OO + o0;
        *(float4*)(op)     = lo;
        *(float4*)(op + 4) = hi;
    }
}

extern "C" void kernel_launch(void* const* d_in, const int* in_sizes, int n_in,
                              void* d_out, int out_size)
{
    (void)in_sizes; (void)n_in; (void)out_size;
    const float* x    = (const float*)d_in[0];
    const float* W    = (const float*)d_in[1];
    const float* bias = (const float*)d_in[2];
    float*       out  = (float*)d_out;

    primarycaps_kernel<<<CC, NTH>>>(x, W, bias, out);
}